// round 1
// baseline (speedup 1.0000x reference)
#include <cuda_runtime.h>
#include <cstdint>

#define B_ 16
#define S_ 1024
#define N_ 4096
#define C_ 768
#define O_ 256

// Scratch (allocation-free rule: __device__ globals)
__device__ int   g_idx[B_ * S_];
__device__ float g_G[(size_t)B_ * S_ * C_];   // gathered features, [M=B*S][C] row-major

// ---------------------------------------------------------------------------
// Kernel 1: argmin over N points per seed.
// One thread per seed (s); block = 128 seeds of one batch; p_last staged in
// smem as float4 (x,y,z,|p|^2) in two 2048-point halves (32KB static smem).
// d2 computed with UNFUSED fp32 ops mirroring the reference expansion:
//   d2 = (sx - 2*dot) + sp
// ---------------------------------------------------------------------------
__global__ __launch_bounds__(128) void argmin_kernel(const float* __restrict__ seed,
                                                     const float* __restrict__ pl) {
    __shared__ float4 p4[2048];
    const int bx = blockIdx.x;
    const int b  = bx >> 3;                      // 8 blocks per batch
    const int s  = ((bx & 7) << 7) + threadIdx.x;

    const float* sp = seed + ((size_t)b * S_ + s) * 3;
    const float x0 = sp[0], x1 = sp[1], x2 = sp[2];
    const float sx = __fadd_rn(__fadd_rn(__fmul_rn(x0, x0), __fmul_rn(x1, x1)),
                               __fmul_rn(x2, x2));

    float best = 3.402823466e38f;
    int   bi   = 0;

    for (int half = 0; half < 2; half++) {
        const int nb = half * 2048;
        for (int n = threadIdx.x; n < 2048; n += 128) {
            const float* pp = pl + ((size_t)b * N_ + nb + n) * 3;
            const float p0 = pp[0], p1 = pp[1], p2 = pp[2];
            const float spp = __fadd_rn(__fadd_rn(__fmul_rn(p0, p0), __fmul_rn(p1, p1)),
                                        __fmul_rn(p2, p2));
            p4[n] = make_float4(p0, p1, p2, spp);
        }
        __syncthreads();
#pragma unroll 8
        for (int n = 0; n < 2048; n++) {
            const float4 q  = p4[n];
            const float dot = __fadd_rn(__fadd_rn(__fmul_rn(x0, q.x), __fmul_rn(x1, q.y)),
                                        __fmul_rn(x2, q.z));
            const float d2  = __fadd_rn(__fsub_rn(sx, __fadd_rn(dot, dot)), q.w);
            if (d2 < best) { best = d2; bi = nb + n; }   // strict < keeps first occurrence
        }
        __syncthreads();
    }
    g_idx[b * S_ + s] = bi;
}

// ---------------------------------------------------------------------------
// Kernel 2: gather f_last[b, c, idx[b,s]] -> g_G[(b*S+s)*C + c]
// Block owns (batch, 8-channel tile, all 1024 seeds). Scattered reads within
// each 16KB channel row amortize in L1; writes staged via smem so they go out
// as two float4 (64B contiguous) per seed -> full write sectors.
// smem: 4KB idx + 32KB tile (static, under 48KB).
// ---------------------------------------------------------------------------
__global__ __launch_bounds__(256) void gather_kernel(const float* __restrict__ f) {
    __shared__ int   sidx[1024];
    __shared__ float tile[8][1024];
    const int b   = blockIdx.x / 96;
    const int c0  = (blockIdx.x % 96) * 8;
    const int tid = threadIdx.x;

    for (int s = tid; s < 1024; s += 256) sidx[s] = g_idx[b * S_ + s];
    __syncthreads();

#pragma unroll
    for (int cl = 0; cl < 8; cl++) {
        const float* row = f + ((size_t)(b * C_ + c0 + cl)) * N_;
        for (int s = tid; s < 1024; s += 256) tile[cl][s] = __ldg(row + sidx[s]);
    }
    __syncthreads();

    for (int s = tid; s < 1024; s += 256) {
        const float4 v0 = make_float4(tile[0][s], tile[1][s], tile[2][s], tile[3][s]);
        const float4 v1 = make_float4(tile[4][s], tile[5][s], tile[6][s], tile[7][s]);
        float4* dst = reinterpret_cast<float4*>(g_G + ((size_t)(b * S_ + s)) * C_ + c0);
        dst[0] = v0; dst[1] = v1;
    }
}

// ---------------------------------------------------------------------------
// Kernel 3: out[b,o,s] = sum_c G[m][c] * W[o][c] + bias[o],  m = b*S + s
// 128x128 block tile, BK=16, 256 threads, 8x8 micro-tile.
// Inner product uses packed fma.rn.f32x2 (FFMA2): 2x fp32 FMA throughput vs
// 3-reg FFMA on sm_103a. s is the packed/fast dimension -> float4 stores along
// s are fully coalesced into the [B,O,S] output layout.
// ---------------------------------------------------------------------------
__device__ __forceinline__ void ffma2(unsigned long long& acc,
                                      unsigned long long a,
                                      unsigned long long b) {
    asm("fma.rn.f32x2 %0, %1, %2, %0;" : "+l"(acc) : "l"(a), "l"(b));
}
__device__ __forceinline__ unsigned long long pack2(float v) {
    unsigned long long r;
    unsigned int u = __float_as_uint(v);
    asm("mov.b64 %0, {%1, %1};" : "=l"(r) : "r"(u));
    return r;
}

__global__ __launch_bounds__(256, 2) void gemm_kernel(const float* __restrict__ Wt,
                                                      const float* __restrict__ bias,
                                                      float* __restrict__ out) {
    __shared__ float As[16][128];   // [k][m]  (m = s-dim)
    __shared__ float Bs[16][128];   // [k][n]  (n = o-dim)

    const int tid = threadIdx.x;
    const int tx  = tid & 15;       // m (s) micro-tile group
    const int ty  = tid >> 4;       // n (o) micro-tile group
    const int m0  = blockIdx.x * 128;
    const int n0  = blockIdx.y * 128;

    const int lrow = tid >> 2;          // 0..63
    const int lcol = (tid & 3) << 2;    // 0,4,8,12

    const float* Ag0 = g_G + (size_t)(m0 + lrow)      * C_ + lcol;
    const float* Ag1 = g_G + (size_t)(m0 + lrow + 64) * C_ + lcol;
    const float* Bg0 = Wt  + (size_t)(n0 + lrow)      * C_ + lcol;
    const float* Bg1 = Wt  + (size_t)(n0 + lrow + 64) * C_ + lcol;

    unsigned long long acc[8][4];
#pragma unroll
    for (int i = 0; i < 8; i++)
#pragma unroll
        for (int p = 0; p < 4; p++) acc[i][p] = 0ull;

    for (int kt = 0; kt < C_; kt += 16) {
        const float4 a0 = *reinterpret_cast<const float4*>(Ag0 + kt);
        const float4 a1 = *reinterpret_cast<const float4*>(Ag1 + kt);
        const float4 b0 = *reinterpret_cast<const float4*>(Bg0 + kt);
        const float4 b1 = *reinterpret_cast<const float4*>(Bg1 + kt);
        __syncthreads();
        As[lcol + 0][lrow]      = a0.x; As[lcol + 1][lrow]      = a0.y;
        As[lcol + 2][lrow]      = a0.z; As[lcol + 3][lrow]      = a0.w;
        As[lcol + 0][lrow + 64] = a1.x; As[lcol + 1][lrow + 64] = a1.y;
        As[lcol + 2][lrow + 64] = a1.z; As[lcol + 3][lrow + 64] = a1.w;
        Bs[lcol + 0][lrow]      = b0.x; Bs[lcol + 1][lrow]      = b0.y;
        Bs[lcol + 2][lrow]      = b0.z; Bs[lcol + 3][lrow]      = b0.w;
        Bs[lcol + 0][lrow + 64] = b1.x; Bs[lcol + 1][lrow + 64] = b1.y;
        Bs[lcol + 2][lrow + 64] = b1.z; Bs[lcol + 3][lrow + 64] = b1.w;
        __syncthreads();
#pragma unroll
        for (int k = 0; k < 16; k++) {
            const ulonglong2 ma = *reinterpret_cast<const ulonglong2*>(&As[k][tx * 8]);
            const ulonglong2 mb = *reinterpret_cast<const ulonglong2*>(&As[k][tx * 8 + 4]);
            const unsigned long long mm[4] = {ma.x, ma.y, mb.x, mb.y};
            const float4 w0 = *reinterpret_cast<const float4*>(&Bs[k][ty * 8]);
            const float4 w1 = *reinterpret_cast<const float4*>(&Bs[k][ty * 8 + 4]);
            const float wv[8] = {w0.x, w0.y, w0.z, w0.w, w1.x, w1.y, w1.z, w1.w};
#pragma unroll
            for (int i = 0; i < 8; i++) {
                const unsigned long long nn = pack2(wv[i]);
#pragma unroll
                for (int p = 0; p < 4; p++) ffma2(acc[i][p], mm[p], nn);
            }
        }
    }

    // Epilogue: unpack, add bias, store coalesced along s.
    const int sg = m0 + tx * 8;
    const int bb = sg >> 10;       // batch (128-row tiles never straddle S=1024)
    const int sl = sg & 1023;
#pragma unroll
    for (int i = 0; i < 8; i++) {
        const int o = n0 + ty * 8 + i;
        const float bo = __ldg(bias + o);
        float r[8];
#pragma unroll
        for (int p = 0; p < 4; p++) {
            unsigned int lo, hi;
            asm("mov.b64 {%0, %1}, %2;" : "=r"(lo), "=r"(hi) : "l"(acc[i][p]));
            r[2 * p]     = __uint_as_float(lo) + bo;
            r[2 * p + 1] = __uint_as_float(hi) + bo;
        }
        float4* dst = reinterpret_cast<float4*>(out + ((size_t)(bb * O_ + o)) * S_ + sl);
        dst[0] = make_float4(r[0], r[1], r[2], r[3]);
        dst[1] = make_float4(r[4], r[5], r[6], r[7]);
    }
}

// ---------------------------------------------------------------------------
extern "C" void kernel_launch(void* const* d_in, const int* in_sizes, int n_in,
                              void* d_out, int out_size) {
    const float* seed = (const float*)d_in[0];   // [16,1024,3]
    const float* pl   = (const float*)d_in[1];   // [16,4096,3]
    const float* fl   = (const float*)d_in[2];   // [16,768,4096]
    const float* Wt   = (const float*)d_in[3];   // [256,768]
    const float* bias = (const float*)d_in[4];   // [256]
    float* out = (float*)d_out;                  // [16,256,1024]

    argmin_kernel<<<128, 128>>>(seed, pl);
    gather_kernel<<<B_ * 96, 256>>>(fl);
    gemm_kernel<<<dim3((B_ * S_) / 128, O_ / 128), 256>>>(Wt, bias, out);
}

// round 3
// speedup vs baseline: 1.2078x; 1.2078x over previous
#include <cuda_runtime.h>
#include <cuda_bf16.h>
#include <cstdint>

#define B_ 16
#define S_ 1024
#define N_ 4096
#define C_ 768
#define O_ 256

// ---------------------------------------------------------------------------
// Scratch (__device__ globals; allocation-free rule)
// ---------------------------------------------------------------------------
__device__ int            g_idx[B_ * S_];
__device__ __nv_bfloat16  g_Ahi[(size_t)B_ * S_ * C_];
__device__ __nv_bfloat16  g_Alo[(size_t)B_ * S_ * C_];
__device__ __nv_bfloat16  g_Bhi[O_ * C_];
__device__ __nv_bfloat16  g_Blo[O_ * C_];

// ---------------------------------------------------------------------------
// Base-ISA (compute_103-safe) PTX helpers: cp.async, ldmatrix, mma.sync
// ---------------------------------------------------------------------------
__device__ __forceinline__ uint32_t smem_u32(const void* p) {
    uint32_t a;
    asm("{ .reg .u64 t; cvta.to.shared.u64 t, %1; cvt.u32.u64 %0, t; }" : "=r"(a) : "l"(p));
    return a;
}
__device__ __forceinline__ void cp16(uint32_t dst, const void* src) {
    asm volatile("cp.async.cg.shared.global [%0], [%1], 16;"
                 :: "r"(dst), "l"(src) : "memory");
}
#define CP_COMMIT() asm volatile("cp.async.commit_group;" ::: "memory")
#define CP_WAIT(n)  asm volatile("cp.async.wait_group %0;" :: "n"(n) : "memory")

__device__ __forceinline__ void ldsm4(uint32_t* r, uint32_t addr) {
    asm volatile("ldmatrix.sync.aligned.m8n8.x4.shared.b16 {%0,%1,%2,%3}, [%4];"
                 : "=r"(r[0]), "=r"(r[1]), "=r"(r[2]), "=r"(r[3]) : "r"(addr));
}
__device__ __forceinline__ void mma_bf16(float* c, const uint32_t* a, const uint32_t* b) {
    asm volatile("mma.sync.aligned.m16n8k16.row.col.f32.bf16.bf16.f32 "
                 "{%0,%1,%2,%3}, {%4,%5,%6,%7}, {%8,%9}, {%0,%1,%2,%3};"
                 : "+f"(c[0]), "+f"(c[1]), "+f"(c[2]), "+f"(c[3])
                 : "r"(a[0]), "r"(a[1]), "r"(a[2]), "r"(a[3]), "r"(b[0]), "r"(b[1]));
}

// ---------------------------------------------------------------------------
// Kernel 1: argmin. 256 thr/block; 2 threads per seed (each scans 2048 pts),
// 4 independent (ordered_d2,n)-key accumulators to break the min chain.
// Per-point arithmetic identical to the round-1 passing kernel.
// ---------------------------------------------------------------------------
__global__ __launch_bounds__(256) void argmin_kernel(const float* __restrict__ seed,
                                                     const float* __restrict__ pl) {
    extern __shared__ float4 p4[];                 // 4096 * 16B = 64KB
    __shared__ unsigned long long merge[128];
    const int bx  = blockIdx.x;
    const int b   = bx >> 3;
    const int tid = threadIdx.x;
    const int grp = tid >> 7;
    const int sl  = tid & 127;
    const int s   = ((bx & 7) << 7) + sl;

    for (int n = tid; n < N_; n += 256) {
        const float* pp = pl + ((size_t)b * N_ + n) * 3;
        const float p0 = pp[0], p1 = pp[1], p2 = pp[2];
        const float spp = __fadd_rn(__fadd_rn(__fmul_rn(p0, p0), __fmul_rn(p1, p1)),
                                    __fmul_rn(p2, p2));
        p4[n] = make_float4(p0, p1, p2, spp);
    }
    const float* sp = seed + ((size_t)b * S_ + s) * 3;
    const float x0 = sp[0], x1 = sp[1], x2 = sp[2];
    const float sx = __fadd_rn(__fadd_rn(__fmul_rn(x0, x0), __fmul_rn(x1, x1)),
                               __fmul_rn(x2, x2));
    __syncthreads();

    unsigned long long best[4] = {~0ull, ~0ull, ~0ull, ~0ull};
    const int nb = grp * 2048;
#pragma unroll 4
    for (int n0 = 0; n0 < 2048; n0 += 4) {
#pragma unroll
        for (int j = 0; j < 4; j++) {
            const int n = nb + n0 + j;
            const float4 q = p4[n];
            const float dot = __fadd_rn(__fadd_rn(__fmul_rn(x0, q.x), __fmul_rn(x1, q.y)),
                                        __fmul_rn(x2, q.z));
            const float d2 = __fadd_rn(__fsub_rn(sx, __fadd_rn(dot, dot)), q.w);
            const unsigned u = __float_as_uint(d2);
            const unsigned ord = u ^ (((unsigned)((int)u >> 31)) | 0x80000000u);
            const unsigned long long key = ((unsigned long long)ord << 32) | (unsigned)n;
            if (key < best[j]) best[j] = key;
        }
    }
    unsigned long long k01 = best[0] < best[1] ? best[0] : best[1];
    unsigned long long k23 = best[2] < best[3] ? best[2] : best[3];
    unsigned long long k = k01 < k23 ? k01 : k23;
    if (grp == 1) merge[sl] = k;
    __syncthreads();
    if (grp == 0) {
        const unsigned long long k2 = merge[sl];
        if (k2 < k) k = k2;
        g_idx[b * S_ + s] = (int)(k & 0xFFFFFFFFu);
    }
}

// ---------------------------------------------------------------------------
// Kernel 2: gather + bf16 hi/lo split.
// ---------------------------------------------------------------------------
__global__ __launch_bounds__(256) void gather_kernel(const float* __restrict__ f) {
    __shared__ int   sidx[1024];
    __shared__ float tile[8][1024];
    const int b   = blockIdx.x / 96;
    const int c0  = (blockIdx.x % 96) * 8;
    const int tid = threadIdx.x;

    for (int s = tid; s < 1024; s += 256) sidx[s] = g_idx[b * S_ + s];
    __syncthreads();
#pragma unroll
    for (int cl = 0; cl < 8; cl++) {
        const float* row = f + ((size_t)(b * C_ + c0 + cl)) * N_;
        for (int s = tid; s < 1024; s += 256) tile[cl][s] = __ldg(row + sidx[s]);
    }
    __syncthreads();

    for (int s = tid; s < 1024; s += 256) {
        unsigned hi[4], lo[4];
#pragma unroll
        for (int p = 0; p < 4; p++) {
            const float v0 = tile[2 * p][s], v1 = tile[2 * p + 1][s];
            const __nv_bfloat16 h0 = __float2bfloat16(v0);
            const __nv_bfloat16 h1 = __float2bfloat16(v1);
            const float r0 = v0 - __bfloat162float(h0);
            const float r1 = v1 - __bfloat162float(h1);
            const __nv_bfloat162 hh = __nv_bfloat162(h0, h1);
            const __nv_bfloat162 ll = __nv_bfloat162(__float2bfloat16(r0), __float2bfloat16(r1));
            hi[p] = *reinterpret_cast<const unsigned*>(&hh);
            lo[p] = *reinterpret_cast<const unsigned*>(&ll);
        }
        const size_t base = ((size_t)(b * S_ + s)) * C_ + c0;
        *reinterpret_cast<uint4*>(&g_Ahi[base]) = make_uint4(hi[0], hi[1], hi[2], hi[3]);
        *reinterpret_cast<uint4*>(&g_Alo[base]) = make_uint4(lo[0], lo[1], lo[2], lo[3]);
    }
}

// ---------------------------------------------------------------------------
// Kernel 2b: split W into bf16 hi/lo.
// ---------------------------------------------------------------------------
__global__ __launch_bounds__(256) void wsplit_kernel(const float* __restrict__ W) {
    const int i = blockIdx.x * 256 + threadIdx.x;
    if (i < O_ * C_) {
        const float v = W[i];
        const __nv_bfloat16 h = __float2bfloat16(v);
        g_Bhi[i] = h;
        g_Blo[i] = __float2bfloat16(v - __bfloat162float(h));
    }
}

// ---------------------------------------------------------------------------
// Kernel 3: mma.sync bf16 GEMM (base-ISA; fallback HMMA pipe on sm_103).
// CTA tile 128(m)x128(n), 256 thr, warp tile m32 x n64 (warps 4m x 2n).
// D = Ah*Bh + Ah*Bl + Al*Bh, fp32 accum. 48 k16 chunks; 4-stage cp.async
// pipeline; smem rows padded to 48B -> conflict-free ldmatrix.
// Per stage: Ah/Al/Bh/Bl each 128 rows x 48B = 6KB -> 24KB; 4 stages = 96KB.
// ---------------------------------------------------------------------------
#define ST_STRIDE 24576
#define ARR_AH 0
#define ARR_AL 6144
#define ARR_BH 12288
#define ARR_BL 18432
#define GEMM_SMEM (4 * ST_STRIDE)

__global__ __launch_bounds__(256, 1) void gemm_kernel(const float* __restrict__ bias,
                                                      float* __restrict__ out) {
    extern __shared__ char smem[];
    const uint32_t sb = smem_u32(smem);
    const int tid  = threadIdx.x;
    const int lane = tid & 31;
    const int wid  = tid >> 5;
    const int warp_m = wid & 3;      // 4 m-warps (m32 each)
    const int warp_n = wid >> 2;     // 2 n-warps (n64 each)
    const int m0 = blockIdx.x * 128;
    const int n0 = blockIdx.y * 128;

    // cp.async assignment: each thread stages one 16B seg of one row per array
    const int crow = tid >> 1;       // 0..127
    const int cseg = tid & 1;        // 0..1
    const __nv_bfloat16* gAh = g_Ahi + (size_t)(m0 + crow) * C_ + cseg * 8;
    const __nv_bfloat16* gAl = g_Alo + (size_t)(m0 + crow) * C_ + cseg * 8;
    const __nv_bfloat16* gBh = g_Bhi + (size_t)(n0 + crow) * C_ + cseg * 8;
    const __nv_bfloat16* gBl = g_Blo + (size_t)(n0 + crow) * C_ + cseg * 8;
    const uint32_t sdst = sb + crow * 48 + cseg * 16;

#define ISSUE(kc, stg)                                              \
    do {                                                            \
        const uint32_t s0 = sdst + (stg) * ST_STRIDE;               \
        const int ko = (kc) * 16;                                   \
        cp16(s0 + ARR_AH, gAh + ko);                                \
        cp16(s0 + ARR_AL, gAl + ko);                                \
        cp16(s0 + ARR_BH, gBh + ko);                                \
        cp16(s0 + ARR_BL, gBl + ko);                                \
    } while (0)

    ISSUE(0, 0); CP_COMMIT();
    ISSUE(1, 1); CP_COMMIT();
    ISSUE(2, 2); CP_COMMIT();

    float acc[2][8][4];
#pragma unroll
    for (int i = 0; i < 2; i++)
#pragma unroll
        for (int j = 0; j < 8; j++)
#pragma unroll
            for (int p = 0; p < 4; p++) acc[i][j][p] = 0.f;

    // ldmatrix lane addressing (within a stage)
    const uint32_t aOff = (uint32_t)((warp_m * 32 + (lane & 7) + ((lane >> 3) & 1) * 8) * 48
                                     + (lane >> 4) * 16);
    const uint32_t bOff = (uint32_t)((warp_n * 64 + (lane & 7) + ((lane >> 4) << 3)) * 48
                                     + ((lane >> 3) & 1) * 16);

#pragma unroll 1
    for (int kc = 0; kc < 48; kc++) {
        __syncthreads();                       // all warps done with chunk kc-1
        if (kc + 3 < 48) ISSUE(kc + 3, (kc + 3) & 3);
        CP_COMMIT();
        CP_WAIT(3);                            // chunk kc landed (own groups)
        __syncthreads();                       // everyone's chunk-kc data visible

        const uint32_t st = sb + (kc & 3) * ST_STRIDE;

        uint32_t a[2][2][4];                   // [split][mt][reg]
        ldsm4(a[0][0], st + ARR_AH + aOff);
        ldsm4(a[0][1], st + ARR_AH + aOff + 16 * 48);
        ldsm4(a[1][0], st + ARR_AL + aOff);
        ldsm4(a[1][1], st + ARR_AL + aOff + 16 * 48);

        uint32_t bb[2][4][4];                  // [split][ntp][reg]
#pragma unroll
        for (int ntp = 0; ntp < 4; ntp++) {
            ldsm4(bb[0][ntp], st + ARR_BH + bOff + ntp * 16 * 48);
            ldsm4(bb[1][ntp], st + ARR_BL + bOff + ntp * 16 * 48);
        }

#pragma unroll
        for (int mt = 0; mt < 2; mt++)
#pragma unroll
            for (int nt = 0; nt < 8; nt++) {
                const int ntp = nt >> 1, h2 = (nt & 1) * 2;
                mma_bf16(acc[mt][nt], a[0][mt], &bb[0][ntp][h2]);   // Ah*Bh
                mma_bf16(acc[mt][nt], a[0][mt], &bb[1][ntp][h2]);   // Ah*Bl
                mma_bf16(acc[mt][nt], a[1][mt], &bb[0][ntp][h2]);   // Al*Bh
            }
    }

    // Epilogue: fragment layout (g = lane>>2 row, t = lane&3 col-pair)
    const int g  = lane >> 2;
    const int t4 = lane & 3;
    const int bbatch = m0 >> 10;               // 128-row tiles never straddle S
#pragma unroll
    for (int mt = 0; mt < 2; mt++) {
        const int m = m0 + warp_m * 32 + mt * 16 + g;
        const int slo = m & 1023;
#pragma unroll
        for (int nt = 0; nt < 8; nt++) {
            const int n = n0 + warp_n * 64 + nt * 8 + t4 * 2;
            const float b0v = __ldg(bias + n);
            const float b1v = __ldg(bias + n + 1);
            float* o0 = out + ((size_t)(bbatch * O_ + n)) * S_ + slo;
            float* o1 = out + ((size_t)(bbatch * O_ + n + 1)) * S_ + slo;
            o0[0] = acc[mt][nt][0] + b0v;
            o1[0] = acc[mt][nt][1] + b1v;
            o0[8] = acc[mt][nt][2] + b0v;
            o1[8] = acc[mt][nt][3] + b1v;
        }
    }
}

// ---------------------------------------------------------------------------
extern "C" void kernel_launch(void* const* d_in, const int* in_sizes, int n_in,
                              void* d_out, int out_size) {
    const float* seed = (const float*)d_in[0];   // [16,1024,3]
    const float* pl   = (const float*)d_in[1];   // [16,4096,3]
    const float* fl   = (const float*)d_in[2];   // [16,768,4096]
    const float* Wt   = (const float*)d_in[3];   // [256,768]
    const float* bias = (const float*)d_in[4];   // [256]
    float* out = (float*)d_out;                  // [16,256,1024]

    cudaFuncSetAttribute(argmin_kernel, cudaFuncAttributeMaxDynamicSharedMemorySize, 65536);
    cudaFuncSetAttribute(gemm_kernel, cudaFuncAttributeMaxDynamicSharedMemorySize, GEMM_SMEM);

    argmin_kernel<<<128, 256, 65536>>>(seed, pl);
    wsplit_kernel<<<(O_ * C_ + 255) / 256, 256>>>(Wt);
    gather_kernel<<<B_ * 96, 256>>>(fl);
    gemm_kernel<<<dim3((B_ * S_) / 128, O_ / 128), 256, GEMM_SMEM>>>(bias, out);
}

// round 4
// speedup vs baseline: 2.2150x; 1.8338x over previous
#include <cuda_runtime.h>
#include <cuda_bf16.h>
#include <cstdint>

#define B_ 16
#define S_ 1024
#define N_ 4096
#define C_ 768
#define O_ 256
#define M_ (B_ * S_)   // 16384

// ---------------------------------------------------------------------------
// Scratch (__device__ globals; allocation-free rule)
// A is stored K-MAJOR: g_Ahi[c][m], m = b*1024 + s  (coalesced gather writes,
// ldmatrix.trans reads in the GEMM).
// ---------------------------------------------------------------------------
__device__ int            g_idx[M_];
__device__ __nv_bfloat16  g_Ahi[(size_t)C_ * M_];
__device__ __nv_bfloat16  g_Alo[(size_t)C_ * M_];
__device__ __nv_bfloat16  g_Bhi[O_ * C_];
__device__ __nv_bfloat16  g_Blo[O_ * C_];

// ---------------------------------------------------------------------------
// Base-ISA (compute_103-safe) PTX helpers
// ---------------------------------------------------------------------------
__device__ __forceinline__ uint32_t smem_u32(const void* p) {
    uint32_t a;
    asm("{ .reg .u64 t; cvta.to.shared.u64 t, %1; cvt.u32.u64 %0, t; }" : "=r"(a) : "l"(p));
    return a;
}
__device__ __forceinline__ void cp16(uint32_t dst, const void* src) {
    asm volatile("cp.async.cg.shared.global [%0], [%1], 16;"
                 :: "r"(dst), "l"(src) : "memory");
}
#define CP_COMMIT() asm volatile("cp.async.commit_group;" ::: "memory")
#define CP_WAIT(n)  asm volatile("cp.async.wait_group %0;" :: "n"(n) : "memory")

__device__ __forceinline__ void ldsm4(uint32_t* r, uint32_t addr) {
    asm volatile("ldmatrix.sync.aligned.m8n8.x4.shared.b16 {%0,%1,%2,%3}, [%4];"
                 : "=r"(r[0]), "=r"(r[1]), "=r"(r[2]), "=r"(r[3]) : "r"(addr));
}
__device__ __forceinline__ void ldsm4t(uint32_t* r, uint32_t addr) {
    asm volatile("ldmatrix.sync.aligned.m8n8.x4.trans.shared.b16 {%0,%1,%2,%3}, [%4];"
                 : "=r"(r[0]), "=r"(r[1]), "=r"(r[2]), "=r"(r[3]) : "r"(addr));
}
__device__ __forceinline__ void mma_bf16(float* c, const uint32_t* a, const uint32_t* b) {
    asm volatile("mma.sync.aligned.m16n8k16.row.col.f32.bf16.bf16.f32 "
                 "{%0,%1,%2,%3}, {%4,%5,%6,%7}, {%8,%9}, {%0,%1,%2,%3};"
                 : "+f"(c[0]), "+f"(c[1]), "+f"(c[2]), "+f"(c[3])
                 : "r"(a[0]), "r"(a[1]), "r"(a[2]), "r"(a[3]), "r"(b[0]), "r"(b[1]));
}

// ---------------------------------------------------------------------------
// Kernel 1: argmin (unchanged from round-3 passing version).
// ---------------------------------------------------------------------------
__global__ __launch_bounds__(256) void argmin_kernel(const float* __restrict__ seed,
                                                     const float* __restrict__ pl) {
    extern __shared__ float4 p4[];                 // 4096 * 16B = 64KB
    __shared__ unsigned long long merge[128];
    const int bx  = blockIdx.x;
    const int b   = bx >> 3;
    const int tid = threadIdx.x;
    const int grp = tid >> 7;
    const int sl  = tid & 127;
    const int s   = ((bx & 7) << 7) + sl;

    for (int n = tid; n < N_; n += 256) {
        const float* pp = pl + ((size_t)b * N_ + n) * 3;
        const float p0 = pp[0], p1 = pp[1], p2 = pp[2];
        const float spp = __fadd_rn(__fadd_rn(__fmul_rn(p0, p0), __fmul_rn(p1, p1)),
                                    __fmul_rn(p2, p2));
        p4[n] = make_float4(p0, p1, p2, spp);
    }
    const float* sp = seed + ((size_t)b * S_ + s) * 3;
    const float x0 = sp[0], x1 = sp[1], x2 = sp[2];
    const float sx = __fadd_rn(__fadd_rn(__fmul_rn(x0, x0), __fmul_rn(x1, x1)),
                               __fmul_rn(x2, x2));
    __syncthreads();

    unsigned long long best[4] = {~0ull, ~0ull, ~0ull, ~0ull};
    const int nb = grp * 2048;
#pragma unroll 4
    for (int n0 = 0; n0 < 2048; n0 += 4) {
#pragma unroll
        for (int j = 0; j < 4; j++) {
            const int n = nb + n0 + j;
            const float4 q = p4[n];
            const float dot = __fadd_rn(__fadd_rn(__fmul_rn(x0, q.x), __fmul_rn(x1, q.y)),
                                        __fmul_rn(x2, q.z));
            const float d2 = __fadd_rn(__fsub_rn(sx, __fadd_rn(dot, dot)), q.w);
            const unsigned u = __float_as_uint(d2);
            const unsigned ord = u ^ (((unsigned)((int)u >> 31)) | 0x80000000u);
            const unsigned long long key = ((unsigned long long)ord << 32) | (unsigned)n;
            if (key < best[j]) best[j] = key;
        }
    }
    unsigned long long k01 = best[0] < best[1] ? best[0] : best[1];
    unsigned long long k23 = best[2] < best[3] ? best[2] : best[3];
    unsigned long long k = k01 < k23 ? k01 : k23;
    if (grp == 1) merge[sl] = k;
    __syncthreads();
    if (grp == 0) {
        const unsigned long long k2 = merge[sl];
        if (k2 < k) k = k2;
        g_idx[b * S_ + s] = (int)(k & 0xFFFFFFFFu);
    }
}

// ---------------------------------------------------------------------------
// Kernel 2: gather, inverted. Block = (batch, 4-channel tile). Stream the 4
// contiguous channel rows (64KB) into smem COALESCED, then scatter-lookup by
// idx from smem. Writes are k-major -> fully coalesced 2B stores.
// ---------------------------------------------------------------------------
__global__ __launch_bounds__(256) void gather_kernel(const float* __restrict__ f) {
    extern __shared__ char gs[];
    float* rows = reinterpret_cast<float*>(gs);            // 4 * 4096 floats
    int*   sidx = reinterpret_cast<int*>(gs + 65536);      // 1024 ints
    const int b   = blockIdx.x / 192;
    const int c0  = (blockIdx.x % 192) * 4;
    const int tid = threadIdx.x;

    for (int s = tid; s < 1024; s += 256) sidx[s] = g_idx[b * S_ + s];
    const float4* src = reinterpret_cast<const float4*>(f + ((size_t)(b * C_ + c0)) * N_);
    float4* dst4 = reinterpret_cast<float4*>(rows);
#pragma unroll 4
    for (int i = tid; i < 4096; i += 256) dst4[i] = src[i];   // 64KB coalesced
    __syncthreads();

#pragma unroll
    for (int c = 0; c < 4; c++) {
        const float* row = rows + c * 4096;
        const size_t obase = (size_t)(c0 + c) * M_ + b * S_;
        for (int s = tid; s < 1024; s += 256) {
            const float v = row[sidx[s]];
            const __nv_bfloat16 h = __float2bfloat16(v);
            g_Ahi[obase + s] = h;
            g_Alo[obase + s] = __float2bfloat16(v - __bfloat162float(h));
        }
    }
}

// ---------------------------------------------------------------------------
// Kernel 2b: split W into bf16 hi/lo (row-major [O][C], unchanged).
// ---------------------------------------------------------------------------
__global__ __launch_bounds__(256) void wsplit_kernel(const float* __restrict__ W) {
    const int i = blockIdx.x * 256 + threadIdx.x;
    if (i < O_ * C_) {
        const float v = W[i];
        const __nv_bfloat16 h = __float2bfloat16(v);
        g_Bhi[i] = h;
        g_Blo[i] = __float2bfloat16(v - __bfloat162float(h));
    }
}

// ---------------------------------------------------------------------------
// Kernel 3: mma.sync bf16 GEMM. CTA 128m x 128n, 256 thr, warp m32 x n64.
// A k-major in gmem and smem (16 k-rows x 256B data, 272B padded stride ->
// conflict-free ldmatrix.trans). B row-major 48B-padded rows (as before).
// 4-stage cp.async, ONE __syncthreads per k-chunk, 2 CTAs/SM.
// Stage: Ah 4352 | Al 4352 | Bh 6144 | Bl 6144 = 20992B; 4 stages = 83968B.
// ---------------------------------------------------------------------------
#define ARR_AH 0
#define ARR_AL 4352
#define ARR_BH 8704
#define ARR_BL 14848
#define STAGE  20992
#define GEMM_SMEM (4 * STAGE)

__global__ __launch_bounds__(256, 2) void gemm_kernel(const float* __restrict__ bias,
                                                      float* __restrict__ out) {
    extern __shared__ char smem[];
    const uint32_t sb = smem_u32(smem);
    const int tid  = threadIdx.x;
    const int lane = tid & 31;
    const int wid  = tid >> 5;
    const int warp_m = wid & 3;      // 4 m-warps (m32 each)
    const int warp_n = wid >> 2;     // 2 n-warps (n64 each)
    const int m0 = blockIdx.x * 128;
    const int n0 = blockIdx.y * 128;

    // cp.async assignment.
    // A (k-major): thread -> (krow = tid>>4, seg = tid&15); both splits.
    const int akrow = tid >> 4;
    const int aseg  = tid & 15;
    const __nv_bfloat16* gAh = g_Ahi + (size_t)akrow * M_ + m0 + aseg * 8;
    const __nv_bfloat16* gAl = g_Alo + (size_t)akrow * M_ + m0 + aseg * 8;
    const uint32_t dA = (uint32_t)(akrow * 272 + aseg * 16);
    // B (row-major): thread -> (row = tid>>1, seg = tid&1); both splits.
    const int brow = tid >> 1;
    const int bseg = tid & 1;
    const __nv_bfloat16* gBh = g_Bhi + (size_t)(n0 + brow) * C_ + bseg * 8;
    const __nv_bfloat16* gBl = g_Blo + (size_t)(n0 + brow) * C_ + bseg * 8;
    const uint32_t dB = (uint32_t)(brow * 48 + bseg * 16);

#define ISSUE(kc, stg)                                                    \
    do {                                                                  \
        const uint32_t s0 = sb + (stg) * STAGE;                           \
        cp16(s0 + ARR_AH + dA, gAh + (size_t)(kc) * (16 * M_));           \
        cp16(s0 + ARR_AL + dA, gAl + (size_t)(kc) * (16 * M_));           \
        cp16(s0 + ARR_BH + dB, gBh + (kc) * 16);                          \
        cp16(s0 + ARR_BL + dB, gBl + (kc) * 16);                          \
    } while (0)

    ISSUE(0, 0); CP_COMMIT();
    ISSUE(1, 1); CP_COMMIT();
    ISSUE(2, 2); CP_COMMIT();

    float acc[2][8][4];
#pragma unroll
    for (int i = 0; i < 2; i++)
#pragma unroll
        for (int j = 0; j < 8; j++)
#pragma unroll
            for (int p = 0; p < 4; p++) acc[i][j][p] = 0.f;

    // ldmatrix.trans A addressing: lane -> k-row (lane&7 | hi8 from lane>>4),
    // m-col block from lane>>3 bit. Register order r0..r3 == a0..a3.
    const uint32_t aOff = (uint32_t)(((lane & 7) + ((lane >> 4) & 1) * 8) * 272
                                     + (warp_m * 32 + ((lane >> 3) & 1) * 8) * 2);
    // ldmatrix B addressing (unchanged; 48B rows).
    const uint32_t bOff = (uint32_t)((warp_n * 64 + (lane & 7) + ((lane >> 4) << 3)) * 48
                                     + ((lane >> 3) & 1) * 16);

#pragma unroll 1
    for (int kc = 0; kc < 48; kc++) {
        CP_WAIT(2);                    // own groups: stage kc landed
        __syncthreads();               // all warps: stage kc visible, kc-1 reads done
        if (kc + 3 < 48) ISSUE(kc + 3, (kc + 3) & 3);   // overwrites slot (kc-1)&3: safe
        CP_COMMIT();

        const uint32_t st = sb + (kc & 3) * STAGE;

        uint32_t a[2][2][4];           // [split][mt][reg]
        ldsm4t(a[0][0], st + ARR_AH + aOff);
        ldsm4t(a[0][1], st + ARR_AH + aOff + 32);   // +16 m-cols
        ldsm4t(a[1][0], st + ARR_AL + aOff);
        ldsm4t(a[1][1], st + ARR_AL + aOff + 32);

        uint32_t bb[2][4][4];          // [split][ntp][reg]
#pragma unroll
        for (int ntp = 0; ntp < 4; ntp++) {
            ldsm4(bb[0][ntp], st + ARR_BH + bOff + ntp * 16 * 48);
            ldsm4(bb[1][ntp], st + ARR_BL + bOff + ntp * 16 * 48);
        }

#pragma unroll
        for (int mt = 0; mt < 2; mt++)
#pragma unroll
            for (int nt = 0; nt < 8; nt++) {
                const int ntp = nt >> 1, h2 = (nt & 1) * 2;
                mma_bf16(acc[mt][nt], a[0][mt], &bb[0][ntp][h2]);   // Ah*Bh
                mma_bf16(acc[mt][nt], a[0][mt], &bb[1][ntp][h2]);   // Ah*Bl
                mma_bf16(acc[mt][nt], a[1][mt], &bb[0][ntp][h2]);   // Al*Bh
            }
    }

    // Epilogue
    const int g  = lane >> 2;
    const int t4 = lane & 3;
    const int bbatch = m0 >> 10;
#pragma unroll
    for (int mt = 0; mt < 2; mt++) {
        const int m = m0 + warp_m * 32 + mt * 16 + g;
        const int slo = m & 1023;
#pragma unroll
        for (int nt = 0; nt < 8; nt++) {
            const int n = n0 + warp_n * 64 + nt * 8 + t4 * 2;
            const float b0v = __ldg(bias + n);
            const float b1v = __ldg(bias + n + 1);
            float* o0 = out + ((size_t)(bbatch * O_ + n)) * S_ + slo;
            float* o1 = out + ((size_t)(bbatch * O_ + n + 1)) * S_ + slo;
            o0[0] = acc[mt][nt][0] + b0v;
            o1[0] = acc[mt][nt][1] + b1v;
            o0[8] = acc[mt][nt][2] + b0v;
            o1[8] = acc[mt][nt][3] + b1v;
        }
    }
}

// ---------------------------------------------------------------------------
extern "C" void kernel_launch(void* const* d_in, const int* in_sizes, int n_in,
                              void* d_out, int out_size) {
    const float* seed = (const float*)d_in[0];   // [16,1024,3]
    const float* pl   = (const float*)d_in[1];   // [16,4096,3]
    const float* fl   = (const float*)d_in[2];   // [16,768,4096]
    const float* Wt   = (const float*)d_in[3];   // [256,768]
    const float* bias = (const float*)d_in[4];   // [256]
    float* out = (float*)d_out;                  // [16,256,1024]

    cudaFuncSetAttribute(argmin_kernel, cudaFuncAttributeMaxDynamicSharedMemorySize, 65536);
    cudaFuncSetAttribute(gather_kernel, cudaFuncAttributeMaxDynamicSharedMemorySize, 69632);
    cudaFuncSetAttribute(gemm_kernel, cudaFuncAttributeMaxDynamicSharedMemorySize, GEMM_SMEM);

    argmin_kernel<<<128, 256, 65536>>>(seed, pl);
    wsplit_kernel<<<(O_ * C_ + 255) / 256, 256>>>(Wt);
    gather_kernel<<<B_ * 192, 256, 69632>>>(fl);
    gemm_kernel<<<dim3(M_ / 128, O_ / 128), 256, GEMM_SMEM>>>(bias, out);
}

// round 5
// speedup vs baseline: 2.5925x; 1.1705x over previous
#include <cuda_runtime.h>
#include <cuda_bf16.h>
#include <cstdint>

#define B_ 16
#define S_ 1024
#define N_ 4096
#define C_ 768
#define O_ 256
#define M_ (B_ * S_)   // 16384

// ---------------------------------------------------------------------------
// Scratch (__device__ globals; allocation-free rule). A is K-MAJOR.
// ---------------------------------------------------------------------------
__device__ int            g_idx[M_];
__device__ __nv_bfloat16  g_Ahi[(size_t)C_ * M_];
__device__ __nv_bfloat16  g_Alo[(size_t)C_ * M_];
__device__ __nv_bfloat16  g_Bhi[O_ * C_];
__device__ __nv_bfloat16  g_Blo[O_ * C_];

// ---------------------------------------------------------------------------
// Base-ISA (compute_103-safe) PTX helpers
// ---------------------------------------------------------------------------
__device__ __forceinline__ uint32_t smem_u32(const void* p) {
    uint32_t a;
    asm("{ .reg .u64 t; cvta.to.shared.u64 t, %1; cvt.u32.u64 %0, t; }" : "=r"(a) : "l"(p));
    return a;
}
__device__ __forceinline__ void cp16(uint32_t dst, const void* src) {
    asm volatile("cp.async.cg.shared.global [%0], [%1], 16;"
                 :: "r"(dst), "l"(src) : "memory");
}
#define CP_COMMIT() asm volatile("cp.async.commit_group;" ::: "memory")
#define CP_WAIT(n)  asm volatile("cp.async.wait_group %0;" :: "n"(n) : "memory")

__device__ __forceinline__ void ldsm4(uint32_t* r, uint32_t addr) {
    asm volatile("ldmatrix.sync.aligned.m8n8.x4.shared.b16 {%0,%1,%2,%3}, [%4];"
                 : "=r"(r[0]), "=r"(r[1]), "=r"(r[2]), "=r"(r[3]) : "r"(addr));
}
__device__ __forceinline__ void ldsm4t(uint32_t* r, uint32_t addr) {
    asm volatile("ldmatrix.sync.aligned.m8n8.x4.trans.shared.b16 {%0,%1,%2,%3}, [%4];"
                 : "=r"(r[0]), "=r"(r[1]), "=r"(r[2]), "=r"(r[3]) : "r"(addr));
}
__device__ __forceinline__ void mma_bf16(float* c, const uint32_t* a, const uint32_t* b) {
    asm volatile("mma.sync.aligned.m16n8k16.row.col.f32.bf16.bf16.f32 "
                 "{%0,%1,%2,%3}, {%4,%5,%6,%7}, {%8,%9}, {%0,%1,%2,%3};"
                 : "+f"(c[0]), "+f"(c[1]), "+f"(c[2]), "+f"(c[3])
                 : "r"(a[0]), "r"(a[1]), "r"(a[2]), "r"(a[3]), "r"(b[0]), "r"(b[1]));
}

// ---------------------------------------------------------------------------
// Kernel 1: argmin (unchanged — exact arithmetic mirror of reference).
// ---------------------------------------------------------------------------
__global__ __launch_bounds__(256) void argmin_kernel(const float* __restrict__ seed,
                                                     const float* __restrict__ pl) {
    extern __shared__ float4 p4[];                 // 4096 * 16B = 64KB
    __shared__ unsigned long long merge[128];
    const int bx  = blockIdx.x;
    const int b   = bx >> 3;
    const int tid = threadIdx.x;
    const int grp = tid >> 7;
    const int sl  = tid & 127;
    const int s   = ((bx & 7) << 7) + sl;

    for (int n = tid; n < N_; n += 256) {
        const float* pp = pl + ((size_t)b * N_ + n) * 3;
        const float p0 = pp[0], p1 = pp[1], p2 = pp[2];
        const float spp = __fadd_rn(__fadd_rn(__fmul_rn(p0, p0), __fmul_rn(p1, p1)),
                                    __fmul_rn(p2, p2));
        p4[n] = make_float4(p0, p1, p2, spp);
    }
    const float* sp = seed + ((size_t)b * S_ + s) * 3;
    const float x0 = sp[0], x1 = sp[1], x2 = sp[2];
    const float sx = __fadd_rn(__fadd_rn(__fmul_rn(x0, x0), __fmul_rn(x1, x1)),
                               __fmul_rn(x2, x2));
    __syncthreads();

    unsigned long long best[4] = {~0ull, ~0ull, ~0ull, ~0ull};
    const int nb = grp * 2048;
#pragma unroll 4
    for (int n0 = 0; n0 < 2048; n0 += 4) {
#pragma unroll
        for (int j = 0; j < 4; j++) {
            const int n = nb + n0 + j;
            const float4 q = p4[n];
            const float dot = __fadd_rn(__fadd_rn(__fmul_rn(x0, q.x), __fmul_rn(x1, q.y)),
                                        __fmul_rn(x2, q.z));
            const float d2 = __fadd_rn(__fsub_rn(sx, __fadd_rn(dot, dot)), q.w);
            const unsigned u = __float_as_uint(d2);
            const unsigned ord = u ^ (((unsigned)((int)u >> 31)) | 0x80000000u);
            const unsigned long long key = ((unsigned long long)ord << 32) | (unsigned)n;
            if (key < best[j]) best[j] = key;
        }
    }
    unsigned long long k01 = best[0] < best[1] ? best[0] : best[1];
    unsigned long long k23 = best[2] < best[3] ? best[2] : best[3];
    unsigned long long k = k01 < k23 ? k01 : k23;
    if (grp == 1) merge[sl] = k;
    __syncthreads();
    if (grp == 0) {
        const unsigned long long k2 = merge[sl];
        if (k2 < k) k = k2;
        g_idx[b * S_ + s] = (int)(k & 0xFFFFFFFFu);
    }
}

// ---------------------------------------------------------------------------
// Kernel 2: gather (stream f coalesced via cp.async, scatter from smem).
// ---------------------------------------------------------------------------
__global__ __launch_bounds__(256) void gather_kernel(const float* __restrict__ f) {
    extern __shared__ char gs[];
    float* rows = reinterpret_cast<float*>(gs);            // 4 * 4096 floats
    int*   sidx = reinterpret_cast<int*>(gs + 65536);      // 1024 ints
    const uint32_t sb = smem_u32(gs);
    const int b   = blockIdx.x / 192;
    const int c0  = (blockIdx.x % 192) * 4;
    const int tid = threadIdx.x;

    // cp.async staging: idx (4KB) + 4 channel rows (64KB), one group.
    cp16(sb + 65536 + tid * 16, &g_idx[b * S_ + tid * 4]);
    const char* src = reinterpret_cast<const char*>(f + ((size_t)(b * C_ + c0)) * N_);
#pragma unroll
    for (int i = 0; i < 16; i++)
        cp16(sb + (tid + i * 256) * 16, src + (tid + i * 256) * 16);
    CP_COMMIT();
    CP_WAIT(0);
    __syncthreads();

#pragma unroll
    for (int c = 0; c < 4; c++) {
        const float* row = rows + c * 4096;
        const size_t obase = (size_t)(c0 + c) * M_ + b * S_;
        for (int s = tid; s < 1024; s += 256) {
            const float v = row[sidx[s]];
            const __nv_bfloat16 h = __float2bfloat16(v);
            g_Ahi[obase + s] = h;
            g_Alo[obase + s] = __float2bfloat16(v - __bfloat162float(h));
        }
    }
}

// ---------------------------------------------------------------------------
// Kernel 2b: split W into bf16 hi/lo.
// ---------------------------------------------------------------------------
__global__ __launch_bounds__(256) void wsplit_kernel(const float* __restrict__ W) {
    const int i = blockIdx.x * 256 + threadIdx.x;
    if (i < O_ * C_) {
        const float v = W[i];
        const __nv_bfloat16 h = __float2bfloat16(v);
        g_Bhi[i] = h;
        g_Blo[i] = __float2bfloat16(v - __bfloat162float(h));
    }
}

// ---------------------------------------------------------------------------
// Kernel 3: mma.sync bf16 GEMM. CTA 128m x 64n, 256 thr, warps 4m x 2n,
// warp tile m32 x n32 -> 32 acc regs -> fits 3 CTAs/SM (85-reg cap).
// 4-stage cp.async ring, 1 sync per k16 chunk (verified structure).
// Stage: Ah 4352 | Al 4352 | Bh 3072 | Bl 3072 = 14848B; 4 stages = 59392B.
// ---------------------------------------------------------------------------
#define ARR_AH 0
#define ARR_AL 4352
#define ARR_BH 8704
#define ARR_BL 11776
#define STAGE  14848
#define GEMM_SMEM (4 * STAGE)

__global__ __launch_bounds__(256, 3) void gemm_kernel(const float* __restrict__ bias,
                                                      float* __restrict__ out) {
    extern __shared__ char smem[];
    const uint32_t sb = smem_u32(smem);
    const int tid  = threadIdx.x;
    const int lane = tid & 31;
    const int wid  = tid >> 5;
    const int warp_m = wid & 3;      // 4 m-warps (m32 each)
    const int warp_n = wid >> 2;     // 2 n-warps (n32 each)
    const int m0 = blockIdx.x * 128;
    const int n0 = blockIdx.y * 64;

    // cp.async assignment.
    // A (k-major): all 256 threads: krow = tid>>4, seg = tid&15.
    const int akrow = tid >> 4;
    const int aseg  = tid & 15;
    const __nv_bfloat16* gAh = g_Ahi + (size_t)akrow * M_ + m0 + aseg * 8;
    const __nv_bfloat16* gAl = g_Alo + (size_t)akrow * M_ + m0 + aseg * 8;
    const uint32_t dA = (uint32_t)(akrow * 272 + aseg * 16);
    // B (row-major, 64 rows x 2 segs): threads 0..127 only.
    const int brow = (tid >> 1) & 63;
    const int bseg = tid & 1;
    const bool bact = tid < 128;
    const __nv_bfloat16* gBh = g_Bhi + (size_t)(n0 + brow) * C_ + bseg * 8;
    const __nv_bfloat16* gBl = g_Blo + (size_t)(n0 + brow) * C_ + bseg * 8;
    const uint32_t dB = (uint32_t)(brow * 48 + bseg * 16);

#define ISSUE(kc, stg)                                                    \
    do {                                                                  \
        const uint32_t s0 = sb + (stg) * STAGE;                           \
        cp16(s0 + ARR_AH + dA, gAh + (size_t)(kc) * (16 * M_));           \
        cp16(s0 + ARR_AL + dA, gAl + (size_t)(kc) * (16 * M_));           \
        if (bact) {                                                       \
            cp16(s0 + ARR_BH + dB, gBh + (kc) * 16);                      \
            cp16(s0 + ARR_BL + dB, gBl + (kc) * 16);                      \
        }                                                                 \
    } while (0)

    ISSUE(0, 0); CP_COMMIT();
    ISSUE(1, 1); CP_COMMIT();
    ISSUE(2, 2); CP_COMMIT();

    float acc[2][4][4];
#pragma unroll
    for (int i = 0; i < 2; i++)
#pragma unroll
        for (int j = 0; j < 4; j++)
#pragma unroll
            for (int p = 0; p < 4; p++) acc[i][j][p] = 0.f;

    // ldmatrix.trans A addressing (verified): k-rows x 272B, m-cols x2B.
    const uint32_t aOff = (uint32_t)(((lane & 7) + ((lane >> 4) & 1) * 8) * 272
                                     + (warp_m * 32 + ((lane >> 3) & 1) * 8) * 2);
    // ldmatrix B addressing (verified): 48B rows.
    const uint32_t bOff = (uint32_t)((warp_n * 32 + (lane & 7) + ((lane >> 4) << 3)) * 48
                                     + ((lane >> 3) & 1) * 16);

#pragma unroll 1
    for (int kc = 0; kc < 48; kc++) {
        CP_WAIT(2);                    // own groups: stage kc landed
        __syncthreads();               // stage kc visible; kc-1 reads done
        if (kc + 3 < 48) ISSUE(kc + 3, (kc + 3) & 3);
        CP_COMMIT();

        const uint32_t st = sb + (kc & 3) * STAGE;

        uint32_t a[2][2][4];           // [split][mt][reg]
        ldsm4t(a[0][0], st + ARR_AH + aOff);
        ldsm4t(a[0][1], st + ARR_AH + aOff + 32);   // +16 m-cols
        ldsm4t(a[1][0], st + ARR_AL + aOff);
        ldsm4t(a[1][1], st + ARR_AL + aOff + 32);

        uint32_t bb[2][2][4];          // [split][ntp][reg]
#pragma unroll
        for (int ntp = 0; ntp < 2; ntp++) {
            ldsm4(bb[0][ntp], st + ARR_BH + bOff + ntp * 16 * 48);
            ldsm4(bb[1][ntp], st + ARR_BL + bOff + ntp * 16 * 48);
        }

#pragma unroll
        for (int mt = 0; mt < 2; mt++)
#pragma unroll
            for (int nt = 0; nt < 4; nt++) {
                const int ntp = nt >> 1, h2 = (nt & 1) * 2;
                mma_bf16(acc[mt][nt], a[0][mt], &bb[0][ntp][h2]);   // Ah*Bh
                mma_bf16(acc[mt][nt], a[0][mt], &bb[1][ntp][h2]);   // Ah*Bl
                mma_bf16(acc[mt][nt], a[1][mt], &bb[0][ntp][h2]);   // Al*Bh
            }
    }

    // Epilogue
    const int g  = lane >> 2;
    const int t4 = lane & 3;
    const int bbatch = m0 >> 10;
#pragma unroll
    for (int mt = 0; mt < 2; mt++) {
        const int m = m0 + warp_m * 32 + mt * 16 + g;
        const int slo = m & 1023;
#pragma unroll
        for (int nt = 0; nt < 4; nt++) {
            const int n = n0 + warp_n * 32 + nt * 8 + t4 * 2;
            const float b0v = __ldg(bias + n);
            const float b1v = __ldg(bias + n + 1);
            float* o0 = out + ((size_t)(bbatch * O_ + n)) * S_ + slo;
            float* o1 = out + ((size_t)(bbatch * O_ + n + 1)) * S_ + slo;
            o0[0] = acc[mt][nt][0] + b0v;
            o1[0] = acc[mt][nt][1] + b1v;
            o0[8] = acc[mt][nt][2] + b0v;
            o1[8] = acc[mt][nt][3] + b1v;
        }
    }
}

// ---------------------------------------------------------------------------
extern "C" void kernel_launch(void* const* d_in, const int* in_sizes, int n_in,
                              void* d_out, int out_size) {
    const float* seed = (const float*)d_in[0];   // [16,1024,3]
    const float* pl   = (const float*)d_in[1];   // [16,4096,3]
    const float* fl   = (const float*)d_in[2];   // [16,768,4096]
    const float* Wt   = (const float*)d_in[3];   // [256,768]
    const float* bias = (const float*)d_in[4];   // [256]
    float* out = (float*)d_out;                  // [16,256,1024]

    cudaFuncSetAttribute(argmin_kernel, cudaFuncAttributeMaxDynamicSharedMemorySize, 65536);
    cudaFuncSetAttribute(gather_kernel, cudaFuncAttributeMaxDynamicSharedMemorySize, 69632);
    cudaFuncSetAttribute(gemm_kernel, cudaFuncAttributeMaxDynamicSharedMemorySize, GEMM_SMEM);

    argmin_kernel<<<128, 256, 65536>>>(seed, pl);
    wsplit_kernel<<<(O_ * C_ + 255) / 256, 256>>>(Wt);
    gather_kernel<<<B_ * 192, 256, 69632>>>(fl);
    gemm_kernel<<<dim3(M_ / 128, O_ / 64), 256, GEMM_SMEM>>>(bias, out);
}

// round 6
// speedup vs baseline: 2.5947x; 1.0008x over previous
#include <cuda_runtime.h>
#include <cuda_bf16.h>
#include <cstdint>

#define B_ 16
#define S_ 1024
#define N_ 4096
#define C_ 768
#define O_ 256
#define M_ (B_ * S_)   // 16384

// ---------------------------------------------------------------------------
// Scratch (__device__ globals; allocation-free rule). A is K-MAJOR.
// ---------------------------------------------------------------------------
__device__ int            g_idx[M_];
__device__ __nv_bfloat16  g_Ahi[(size_t)C_ * M_];
__device__ __nv_bfloat16  g_Alo[(size_t)C_ * M_];
__device__ __nv_bfloat16  g_Bhi[O_ * C_];
__device__ __nv_bfloat16  g_Blo[O_ * C_];

// ---------------------------------------------------------------------------
// Base-ISA (compute_103-safe) PTX helpers
// ---------------------------------------------------------------------------
__device__ __forceinline__ uint32_t smem_u32(const void* p) {
    uint32_t a;
    asm("{ .reg .u64 t; cvta.to.shared.u64 t, %1; cvt.u32.u64 %0, t; }" : "=r"(a) : "l"(p));
    return a;
}
__device__ __forceinline__ void cp16(uint32_t dst, const void* src) {
    asm volatile("cp.async.cg.shared.global [%0], [%1], 16;"
                 :: "r"(dst), "l"(src) : "memory");
}
#define CP_COMMIT() asm volatile("cp.async.commit_group;" ::: "memory")
#define CP_WAIT(n)  asm volatile("cp.async.wait_group %0;" :: "n"(n) : "memory")

__device__ __forceinline__ void ldsm4(uint32_t* r, uint32_t addr) {
    asm volatile("ldmatrix.sync.aligned.m8n8.x4.shared.b16 {%0,%1,%2,%3}, [%4];"
                 : "=r"(r[0]), "=r"(r[1]), "=r"(r[2]), "=r"(r[3]) : "r"(addr));
}
__device__ __forceinline__ void ldsm4t(uint32_t* r, uint32_t addr) {
    asm volatile("ldmatrix.sync.aligned.m8n8.x4.trans.shared.b16 {%0,%1,%2,%3}, [%4];"
                 : "=r"(r[0]), "=r"(r[1]), "=r"(r[2]), "=r"(r[3]) : "r"(addr));
}
__device__ __forceinline__ void mma_bf16(float* c, const uint32_t* a, const uint32_t* b) {
    asm volatile("mma.sync.aligned.m16n8k16.row.col.f32.bf16.bf16.f32 "
                 "{%0,%1,%2,%3}, {%4,%5,%6,%7}, {%8,%9}, {%0,%1,%2,%3};"
                 : "+f"(c[0]), "+f"(c[1]), "+f"(c[2]), "+f"(c[3])
                 : "r"(a[0]), "r"(a[1]), "r"(a[2]), "r"(a[3]), "r"(b[0]), "r"(b[1]));
}

// ---------------------------------------------------------------------------
// Kernel 1: argmin. 256 blocks (16/batch, 64 seeds each), 256 thr: 4 groups
// scan 1024 pts each per seed, 4 independent packed-key accumulators.
// Per-point arithmetic EXACTLY mirrors the reference (unfused mul/add).
// ---------------------------------------------------------------------------
__global__ __launch_bounds__(256) void argmin_kernel(const float* __restrict__ seed,
                                                     const float* __restrict__ pl) {
    extern __shared__ float4 p4[];                 // 4096 * 16B = 64KB
    __shared__ unsigned long long merge[4][64];
    const int bx  = blockIdx.x;
    const int b   = bx >> 4;                       // 16 blocks per batch
    const int tid = threadIdx.x;
    const int grp = tid >> 6;                      // 0..3
    const int sl  = tid & 63;
    const int s   = ((bx & 15) << 6) + sl;

    for (int n = tid; n < N_; n += 256) {
        const float* pp = pl + ((size_t)b * N_ + n) * 3;
        const float p0 = pp[0], p1 = pp[1], p2 = pp[2];
        const float spp = __fadd_rn(__fadd_rn(__fmul_rn(p0, p0), __fmul_rn(p1, p1)),
                                    __fmul_rn(p2, p2));
        p4[n] = make_float4(p0, p1, p2, spp);
    }
    const float* sp = seed + ((size_t)b * S_ + s) * 3;
    const float x0 = sp[0], x1 = sp[1], x2 = sp[2];
    const float sx = __fadd_rn(__fadd_rn(__fmul_rn(x0, x0), __fmul_rn(x1, x1)),
                               __fmul_rn(x2, x2));
    __syncthreads();

    unsigned long long best[4] = {~0ull, ~0ull, ~0ull, ~0ull};
    const int nb = grp * 1024;
#pragma unroll 4
    for (int n0 = 0; n0 < 1024; n0 += 4) {
#pragma unroll
        for (int j = 0; j < 4; j++) {
            const int n = nb + n0 + j;
            const float4 q = p4[n];
            const float dot = __fadd_rn(__fadd_rn(__fmul_rn(x0, q.x), __fmul_rn(x1, q.y)),
                                        __fmul_rn(x2, q.z));
            const float d2 = __fadd_rn(__fsub_rn(sx, __fadd_rn(dot, dot)), q.w);
            const unsigned u = __float_as_uint(d2);
            const unsigned ord = u ^ (((unsigned)((int)u >> 31)) | 0x80000000u);
            const unsigned long long key = ((unsigned long long)ord << 32) | (unsigned)n;
            if (key < best[j]) best[j] = key;
        }
    }
    unsigned long long k01 = best[0] < best[1] ? best[0] : best[1];
    unsigned long long k23 = best[2] < best[3] ? best[2] : best[3];
    unsigned long long k = k01 < k23 ? k01 : k23;
    merge[grp][sl] = k;
    __syncthreads();
    if (grp == 0) {
        unsigned long long k1 = merge[1][sl];
        unsigned long long k2 = merge[2][sl];
        unsigned long long k3 = merge[3][sl];
        if (k1 < k) k = k1;
        if (k2 < k) k = k2;
        if (k3 < k) k = k3;
        g_idx[b * S_ + s] = (int)(k & 0xFFFFFFFFu);
    }
}

// ---------------------------------------------------------------------------
// Kernel 2: gather (stream f coalesced via cp.async, scatter from smem).
// ---------------------------------------------------------------------------
__global__ __launch_bounds__(256) void gather_kernel(const float* __restrict__ f) {
    extern __shared__ char gs[];
    float* rows = reinterpret_cast<float*>(gs);            // 4 * 4096 floats
    int*   sidx = reinterpret_cast<int*>(gs + 65536);      // 1024 ints
    const uint32_t sb = smem_u32(gs);
    const int b   = blockIdx.x / 192;
    const int c0  = (blockIdx.x % 192) * 4;
    const int tid = threadIdx.x;

    cp16(sb + 65536 + tid * 16, &g_idx[b * S_ + tid * 4]);
    const char* src = reinterpret_cast<const char*>(f + ((size_t)(b * C_ + c0)) * N_);
#pragma unroll
    for (int i = 0; i < 16; i++)
        cp16(sb + (tid + i * 256) * 16, src + (tid + i * 256) * 16);
    CP_COMMIT();
    CP_WAIT(0);
    __syncthreads();

#pragma unroll
    for (int c = 0; c < 4; c++) {
        const float* row = rows + c * 4096;
        const size_t obase = (size_t)(c0 + c) * M_ + b * S_;
        for (int s = tid; s < 1024; s += 256) {
            const float v = row[sidx[s]];
            const __nv_bfloat16 h = __float2bfloat16(v);
            g_Ahi[obase + s] = h;
            g_Alo[obase + s] = __float2bfloat16(v - __bfloat162float(h));
        }
    }
}

// ---------------------------------------------------------------------------
// Kernel 2b: split W into bf16 hi/lo.
// ---------------------------------------------------------------------------
__global__ __launch_bounds__(256) void wsplit_kernel(const float* __restrict__ W) {
    const int i = blockIdx.x * 256 + threadIdx.x;
    if (i < O_ * C_) {
        const float v = W[i];
        const __nv_bfloat16 h = __float2bfloat16(v);
        g_Bhi[i] = h;
        g_Blo[i] = __float2bfloat16(v - __bfloat162float(h));
    }
}

// ---------------------------------------------------------------------------
// Kernel 3: mma.sync bf16 GEMM. CTA 256m x 64n, 256 thr, warps 4m x 2n,
// warp tile m64 x n32 -> 48 MMAs + 12 ldsm per k16 chunk per warp.
// Grid 64x4 = 256 CTAs, 2 CTAs/SM -> single wave.
// A k-major: 16 k-rows x 512B data, 528B padded stride (528 mod 128 = 16,
// same conflict-free ldmatrix.trans pattern as verified 272).
// Stage: Ah 8448 | Al 8448 | Bh 3072 | Bl 3072 = 23040B; 4 stages = 92160B.
// ---------------------------------------------------------------------------
#define ARR_AH 0
#define ARR_AL 8448
#define ARR_BH 16896
#define ARR_BL 19968
#define STAGE  23040
#define GEMM_SMEM (4 * STAGE)

__global__ __launch_bounds__(256, 2) void gemm_kernel(const float* __restrict__ bias,
                                                      float* __restrict__ out) {
    extern __shared__ char smem[];
    const uint32_t sb = smem_u32(smem);
    const int tid  = threadIdx.x;
    const int lane = tid & 31;
    const int wid  = tid >> 5;
    const int warp_m = wid & 3;      // 4 m-warps (m64 each)
    const int warp_n = wid >> 2;     // 2 n-warps (n32 each)
    const int m0 = blockIdx.x * 256;
    const int n0 = blockIdx.y * 64;

    // cp.async assignment.
    // A (k-major): krow = tid>>4 (0..15), seg = tid&15; each thread also does
    // seg+16 (m +128). dA stride 528B per k-row.
    const int akrow = tid >> 4;
    const int aseg  = tid & 15;
    const __nv_bfloat16* gAh = g_Ahi + (size_t)akrow * M_ + m0 + aseg * 8;
    const __nv_bfloat16* gAl = g_Alo + (size_t)akrow * M_ + m0 + aseg * 8;
    const uint32_t dA = (uint32_t)(akrow * 528 + aseg * 16);
    // B (row-major, 64 rows x 2 segs): threads 0..127 only.
    const int brow = (tid >> 1) & 63;
    const int bseg = tid & 1;
    const bool bact = tid < 128;
    const __nv_bfloat16* gBh = g_Bhi + (size_t)(n0 + brow) * C_ + bseg * 8;
    const __nv_bfloat16* gBl = g_Blo + (size_t)(n0 + brow) * C_ + bseg * 8;
    const uint32_t dB = (uint32_t)(brow * 48 + bseg * 16);

#define ISSUE(kc, stg)                                                    \
    do {                                                                  \
        const uint32_t s0 = sb + (stg) * STAGE;                           \
        const size_t ga = (size_t)(kc) * (16 * M_);                       \
        cp16(s0 + ARR_AH + dA,       gAh + ga);                           \
        cp16(s0 + ARR_AH + dA + 256, gAh + ga + 128);                     \
        cp16(s0 + ARR_AL + dA,       gAl + ga);                           \
        cp16(s0 + ARR_AL + dA + 256, gAl + ga + 128);                     \
        if (bact) {                                                       \
            cp16(s0 + ARR_BH + dB, gBh + (kc) * 16);                      \
            cp16(s0 + ARR_BL + dB, gBl + (kc) * 16);                      \
        }                                                                 \
    } while (0)

    ISSUE(0, 0); CP_COMMIT();
    ISSUE(1, 1); CP_COMMIT();
    ISSUE(2, 2); CP_COMMIT();

    float acc[4][4][4];
#pragma unroll
    for (int i = 0; i < 4; i++)
#pragma unroll
        for (int j = 0; j < 4; j++)
#pragma unroll
            for (int p = 0; p < 4; p++) acc[i][j][p] = 0.f;

    // ldmatrix.trans A addressing: k-rows x 528B, m-cols x 2B.
    const uint32_t aOff = (uint32_t)(((lane & 7) + ((lane >> 4) & 1) * 8) * 528
                                     + (warp_m * 64 + ((lane >> 3) & 1) * 8) * 2);
    // ldmatrix B addressing: 48B rows.
    const uint32_t bOff = (uint32_t)((warp_n * 32 + (lane & 7) + ((lane >> 4) << 3)) * 48
                                     + ((lane >> 3) & 1) * 16);

#pragma unroll 1
    for (int kc = 0; kc < 48; kc++) {
        CP_WAIT(2);                    // own groups: stage kc landed
        __syncthreads();               // stage kc visible; kc-1 reads done
        if (kc + 3 < 48) ISSUE(kc + 3, (kc + 3) & 3);
        CP_COMMIT();

        const uint32_t st = sb + (kc & 3) * STAGE;

        uint32_t bb[2][2][4];          // [split][ntp][reg]
#pragma unroll
        for (int ntp = 0; ntp < 2; ntp++) {
            ldsm4(bb[0][ntp], st + ARR_BH + bOff + ntp * 16 * 48);
            ldsm4(bb[1][ntp], st + ARR_BL + bOff + ntp * 16 * 48);
        }

#pragma unroll
        for (int mt = 0; mt < 4; mt++) {
            uint32_t ah[4], al[4];
            ldsm4t(ah, st + ARR_AH + aOff + mt * 32);   // +16 m-cols per mt
            ldsm4t(al, st + ARR_AL + aOff + mt * 32);
#pragma unroll
            for (int nt = 0; nt < 4; nt++) {
                const int ntp = nt >> 1, h2 = (nt & 1) * 2;
                mma_bf16(acc[mt][nt], ah, &bb[0][ntp][h2]);   // Ah*Bh
                mma_bf16(acc[mt][nt], ah, &bb[1][ntp][h2]);   // Ah*Bl
                mma_bf16(acc[mt][nt], al, &bb[0][ntp][h2]);   // Al*Bh
            }
        }
    }

    // Epilogue
    const int g  = lane >> 2;
    const int t4 = lane & 3;
    const int bbatch = m0 >> 10;       // 256-row tiles never straddle a batch
#pragma unroll
    for (int mt = 0; mt < 4; mt++) {
        const int m = m0 + warp_m * 64 + mt * 16 + g;
        const int slo = m & 1023;
#pragma unroll
        for (int nt = 0; nt < 4; nt++) {
            const int n = n0 + warp_n * 32 + nt * 8 + t4 * 2;
            const float b0v = __ldg(bias + n);
            const float b1v = __ldg(bias + n + 1);
            float* o0 = out + ((size_t)(bbatch * O_ + n)) * S_ + slo;
            float* o1 = out + ((size_t)(bbatch * O_ + n + 1)) * S_ + slo;
            o0[0] = acc[mt][nt][0] + b0v;
            o1[0] = acc[mt][nt][1] + b1v;
            o0[8] = acc[mt][nt][2] + b0v;
            o1[8] = acc[mt][nt][3] + b1v;
        }
    }
}

// ---------------------------------------------------------------------------
extern "C" void kernel_launch(void* const* d_in, const int* in_sizes, int n_in,
                              void* d_out, int out_size) {
    const float* seed = (const float*)d_in[0];   // [16,1024,3]
    const float* pl   = (const float*)d_in[1];   // [16,4096,3]
    const float* fl   = (const float*)d_in[2];   // [16,768,4096]
    const float* Wt   = (const float*)d_in[3];   // [256,768]
    const float* bias = (const float*)d_in[4];   // [256]
    float* out = (float*)d_out;                  // [16,256,1024]

    cudaFuncSetAttribute(argmin_kernel, cudaFuncAttributeMaxDynamicSharedMemorySize, 65536);
    cudaFuncSetAttribute(gather_kernel, cudaFuncAttributeMaxDynamicSharedMemorySize, 69632);
    cudaFuncSetAttribute(gemm_kernel, cudaFuncAttributeMaxDynamicSharedMemorySize, GEMM_SMEM);

    argmin_kernel<<<256, 256, 65536>>>(seed, pl);
    wsplit_kernel<<<(O_ * C_ + 255) / 256, 256>>>(Wt);
    gather_kernel<<<B_ * 192, 256, 69632>>>(fl);
    gemm_kernel<<<dim3(M_ / 256, O_ / 64), 256, GEMM_SMEM>>>(bias, out);
}

// round 7
// speedup vs baseline: 3.0170x; 1.1628x over previous
#include <cuda_runtime.h>
#include <cuda_bf16.h>
#include <cuda_fp16.h>
#include <cstdint>

#define B_ 16
#define S_ 1024
#define N_ 4096
#define C_ 768
#define O_ 256
#define M_ (B_ * S_)   // 16384

// ---------------------------------------------------------------------------
// Scratch (__device__ globals; allocation-free rule). A is K-MAJOR, fp16.
// ---------------------------------------------------------------------------
__device__ int      g_idx[M_];
__device__ __half   g_Af[(size_t)C_ * M_];
__device__ __half   g_Bhi[O_ * C_];
__device__ __half   g_Blo[O_ * C_];

// ---------------------------------------------------------------------------
// Base-ISA (compute_103-safe) PTX helpers
// ---------------------------------------------------------------------------
__device__ __forceinline__ uint32_t smem_u32(const void* p) {
    uint32_t a;
    asm("{ .reg .u64 t; cvta.to.shared.u64 t, %1; cvt.u32.u64 %0, t; }" : "=r"(a) : "l"(p));
    return a;
}
__device__ __forceinline__ void cp16(uint32_t dst, const void* src) {
    asm volatile("cp.async.cg.shared.global [%0], [%1], 16;"
                 :: "r"(dst), "l"(src) : "memory");
}
#define CP_COMMIT() asm volatile("cp.async.commit_group;" ::: "memory")
#define CP_WAIT(n)  asm volatile("cp.async.wait_group %0;" :: "n"(n) : "memory")

__device__ __forceinline__ void ldsm4(uint32_t* r, uint32_t addr) {
    asm volatile("ldmatrix.sync.aligned.m8n8.x4.shared.b16 {%0,%1,%2,%3}, [%4];"
                 : "=r"(r[0]), "=r"(r[1]), "=r"(r[2]), "=r"(r[3]) : "r"(addr));
}
__device__ __forceinline__ void ldsm4t(uint32_t* r, uint32_t addr) {
    asm volatile("ldmatrix.sync.aligned.m8n8.x4.trans.shared.b16 {%0,%1,%2,%3}, [%4];"
                 : "=r"(r[0]), "=r"(r[1]), "=r"(r[2]), "=r"(r[3]) : "r"(addr));
}
__device__ __forceinline__ void mma_f16(float* c, const uint32_t* a, const uint32_t* b) {
    asm volatile("mma.sync.aligned.m16n8k16.row.col.f32.f16.f16.f32 "
                 "{%0,%1,%2,%3}, {%4,%5,%6,%7}, {%8,%9}, {%0,%1,%2,%3};"
                 : "+f"(c[0]), "+f"(c[1]), "+f"(c[2]), "+f"(c[3])
                 : "r"(a[0]), "r"(a[1]), "r"(a[2]), "r"(a[3]), "r"(b[0]), "r"(b[1]));
}

// ---------------------------------------------------------------------------
// Kernel 1: argmin (round-6 version, exact arithmetic mirror of reference).
// ---------------------------------------------------------------------------
__global__ __launch_bounds__(256) void argmin_kernel(const float* __restrict__ seed,
                                                     const float* __restrict__ pl) {
    extern __shared__ float4 p4[];                 // 4096 * 16B = 64KB
    __shared__ unsigned long long merge[4][64];
    const int bx  = blockIdx.x;
    const int b   = bx >> 4;                       // 16 blocks per batch
    const int tid = threadIdx.x;
    const int grp = tid >> 6;                      // 0..3
    const int sl  = tid & 63;
    const int s   = ((bx & 15) << 6) + sl;

    for (int n = tid; n < N_; n += 256) {
        const float* pp = pl + ((size_t)b * N_ + n) * 3;
        const float p0 = pp[0], p1 = pp[1], p2 = pp[2];
        const float spp = __fadd_rn(__fadd_rn(__fmul_rn(p0, p0), __fmul_rn(p1, p1)),
                                    __fmul_rn(p2, p2));
        p4[n] = make_float4(p0, p1, p2, spp);
    }
    const float* sp = seed + ((size_t)b * S_ + s) * 3;
    const float x0 = sp[0], x1 = sp[1], x2 = sp[2];
    const float sx = __fadd_rn(__fadd_rn(__fmul_rn(x0, x0), __fmul_rn(x1, x1)),
                               __fmul_rn(x2, x2));
    __syncthreads();

    unsigned long long best[4] = {~0ull, ~0ull, ~0ull, ~0ull};
    const int nb = grp * 1024;
#pragma unroll 4
    for (int n0 = 0; n0 < 1024; n0 += 4) {
#pragma unroll
        for (int j = 0; j < 4; j++) {
            const int n = nb + n0 + j;
            const float4 q = p4[n];
            const float dot = __fadd_rn(__fadd_rn(__fmul_rn(x0, q.x), __fmul_rn(x1, q.y)),
                                        __fmul_rn(x2, q.z));
            const float d2 = __fadd_rn(__fsub_rn(sx, __fadd_rn(dot, dot)), q.w);
            const unsigned u = __float_as_uint(d2);
            const unsigned ord = u ^ (((unsigned)((int)u >> 31)) | 0x80000000u);
            const unsigned long long key = ((unsigned long long)ord << 32) | (unsigned)n;
            if (key < best[j]) best[j] = key;
        }
    }
    unsigned long long k01 = best[0] < best[1] ? best[0] : best[1];
    unsigned long long k23 = best[2] < best[3] ? best[2] : best[3];
    unsigned long long k = k01 < k23 ? k01 : k23;
    merge[grp][sl] = k;
    __syncthreads();
    if (grp == 0) {
        unsigned long long k1 = merge[1][sl];
        unsigned long long k2 = merge[2][sl];
        unsigned long long k3 = merge[3][sl];
        if (k1 < k) k = k1;
        if (k2 < k) k = k2;
        if (k3 < k) k = k3;
        g_idx[b * S_ + s] = (int)(k & 0xFFFFFFFFu);
    }
}

// ---------------------------------------------------------------------------
// Kernel 2: gather (stream f coalesced via cp.async, scatter fp16 from smem).
// ---------------------------------------------------------------------------
__global__ __launch_bounds__(256) void gather_kernel(const float* __restrict__ f) {
    extern __shared__ char gs[];
    float* rows = reinterpret_cast<float*>(gs);            // 4 * 4096 floats
    int*   sidx = reinterpret_cast<int*>(gs + 65536);      // 1024 ints
    const uint32_t sb = smem_u32(gs);
    const int b   = blockIdx.x / 192;
    const int c0  = (blockIdx.x % 192) * 4;
    const int tid = threadIdx.x;

    cp16(sb + 65536 + tid * 16, &g_idx[b * S_ + tid * 4]);
    const char* src = reinterpret_cast<const char*>(f + ((size_t)(b * C_ + c0)) * N_);
#pragma unroll
    for (int i = 0; i < 16; i++)
        cp16(sb + (tid + i * 256) * 16, src + (tid + i * 256) * 16);
    CP_COMMIT();
    CP_WAIT(0);
    __syncthreads();

#pragma unroll
    for (int c = 0; c < 4; c++) {
        const float* row = rows + c * 4096;
        const size_t obase = (size_t)(c0 + c) * M_ + b * S_;
        for (int s = tid; s < 1024; s += 256)
            g_Af[obase + s] = __float2half(row[sidx[s]]);
    }
}

// ---------------------------------------------------------------------------
// Kernel 2b: split W into fp16 hi/lo.
// ---------------------------------------------------------------------------
__global__ __launch_bounds__(256) void wsplit_kernel(const float* __restrict__ W) {
    const int i = blockIdx.x * 256 + threadIdx.x;
    if (i < O_ * C_) {
        const float v = W[i];
        const __half h = __float2half(v);
        g_Bhi[i] = h;
        g_Blo[i] = __float2half(v - __half2float(h));
    }
}

// ---------------------------------------------------------------------------
// Kernel 3: mma.sync fp16 GEMM, 2-term W-split: D = Af*Bh + Af*Bl.
// Round-5 geometry (proven best): CTA 128m x 64n, 256 thr, warps 4m x 2n,
// warp tile m32 x n32, 4-stage cp.async ring, 1 sync per k16 chunk,
// 3 CTAs/SM. A k-major 272B-padded rows (verified conflict-free ldsm.trans).
// Stage: Af 4352 | Bh 3072 | Bl 3072 = 10496B; 4 stages = 41984B.
// ---------------------------------------------------------------------------
#define ARR_AF 0
#define ARR_BH 4352
#define ARR_BL 7424
#define STAGE  10496
#define GEMM_SMEM (4 * STAGE)

__global__ __launch_bounds__(256, 3) void gemm_kernel(const float* __restrict__ bias,
                                                      float* __restrict__ out) {
    extern __shared__ char smem[];
    const uint32_t sb = smem_u32(smem);
    const int tid  = threadIdx.x;
    const int lane = tid & 31;
    const int wid  = tid >> 5;
    const int warp_m = wid & 3;      // 4 m-warps (m32 each)
    const int warp_n = wid >> 2;     // 2 n-warps (n32 each)
    const int m0 = blockIdx.x * 128;
    const int n0 = blockIdx.y * 64;

    // cp.async assignment.
    // A (k-major): krow = tid>>4 (0..15), seg = tid&15.
    const int akrow = tid >> 4;
    const int aseg  = tid & 15;
    const __half* gA = g_Af + (size_t)akrow * M_ + m0 + aseg * 8;
    const uint32_t dA = (uint32_t)(akrow * 272 + aseg * 16);
    // B (row-major, 64 rows x 2 segs): threads 0..127 only.
    const int brow = (tid >> 1) & 63;
    const int bseg = tid & 1;
    const bool bact = tid < 128;
    const __half* gBh = g_Bhi + (size_t)(n0 + brow) * C_ + bseg * 8;
    const __half* gBl = g_Blo + (size_t)(n0 + brow) * C_ + bseg * 8;
    const uint32_t dB = (uint32_t)(brow * 48 + bseg * 16);

#define ISSUE(kc, stg)                                                    \
    do {                                                                  \
        const uint32_t s0 = sb + (stg) * STAGE;                           \
        cp16(s0 + ARR_AF + dA, gA + (size_t)(kc) * (16 * M_));            \
        if (bact) {                                                       \
            cp16(s0 + ARR_BH + dB, gBh + (kc) * 16);                      \
            cp16(s0 + ARR_BL + dB, gBl + (kc) * 16);                      \
        }                                                                 \
    } while (0)

    ISSUE(0, 0); CP_COMMIT();
    ISSUE(1, 1); CP_COMMIT();
    ISSUE(2, 2); CP_COMMIT();

    float acc[2][4][4];
#pragma unroll
    for (int i = 0; i < 2; i++)
#pragma unroll
        for (int j = 0; j < 4; j++)
#pragma unroll
            for (int p = 0; p < 4; p++) acc[i][j][p] = 0.f;

    // ldmatrix.trans A addressing (verified): k-rows x 272B, m-cols x 2B.
    const uint32_t aOff = (uint32_t)(((lane & 7) + ((lane >> 4) & 1) * 8) * 272
                                     + (warp_m * 32 + ((lane >> 3) & 1) * 8) * 2);
    // ldmatrix B addressing (verified): 48B rows.
    const uint32_t bOff = (uint32_t)((warp_n * 32 + (lane & 7) + ((lane >> 4) << 3)) * 48
                                     + ((lane >> 3) & 1) * 16);

#pragma unroll 1
    for (int kc = 0; kc < 48; kc++) {
        CP_WAIT(2);                    // own groups: stage kc landed
        __syncthreads();               // stage kc visible; kc-1 reads done
        if (kc + 3 < 48) ISSUE(kc + 3, (kc + 3) & 3);
        CP_COMMIT();

        const uint32_t st = sb + (kc & 3) * STAGE;

        uint32_t a[2][4];              // [mt][reg]
        ldsm4t(a[0], st + ARR_AF + aOff);
        ldsm4t(a[1], st + ARR_AF + aOff + 32);      // +16 m-cols

        uint32_t bb[2][2][4];          // [split][ntp][reg]
#pragma unroll
        for (int ntp = 0; ntp < 2; ntp++) {
            ldsm4(bb[0][ntp], st + ARR_BH + bOff + ntp * 16 * 48);
            ldsm4(bb[1][ntp], st + ARR_BL + bOff + ntp * 16 * 48);
        }

#pragma unroll
        for (int mt = 0; mt < 2; mt++)
#pragma unroll
            for (int nt = 0; nt < 4; nt++) {
                const int ntp = nt >> 1, h2 = (nt & 1) * 2;
                mma_f16(acc[mt][nt], a[mt], &bb[0][ntp][h2]);   // Af*Bh
                mma_f16(acc[mt][nt], a[mt], &bb[1][ntp][h2]);   // Af*Bl
            }
    }

    // Epilogue
    const int g  = lane >> 2;
    const int t4 = lane & 3;
    const int bbatch = m0 >> 10;
#pragma unroll
    for (int mt = 0; mt < 2; mt++) {
        const int m = m0 + warp_m * 32 + mt * 16 + g;
        const int slo = m & 1023;
#pragma unroll
        for (int nt = 0; nt < 4; nt++) {
            const int n = n0 + warp_n * 32 + nt * 8 + t4 * 2;
            const float b0v = __ldg(bias + n);
            const float b1v = __ldg(bias + n + 1);
            float* o0 = out + ((size_t)(bbatch * O_ + n)) * S_ + slo;
            float* o1 = out + ((size_t)(bbatch * O_ + n + 1)) * S_ + slo;
            o0[0] = acc[mt][nt][0] + b0v;
            o1[0] = acc[mt][nt][1] + b1v;
            o0[8] = acc[mt][nt][2] + b0v;
            o1[8] = acc[mt][nt][3] + b1v;
        }
    }
}

// ---------------------------------------------------------------------------
extern "C" void kernel_launch(void* const* d_in, const int* in_sizes, int n_in,
                              void* d_out, int out_size) {
    const float* seed = (const float*)d_in[0];   // [16,1024,3]
    const float* pl   = (const float*)d_in[1];   // [16,4096,3]
    const float* fl   = (const float*)d_in[2];   // [16,768,4096]
    const float* Wt   = (const float*)d_in[3];   // [256,768]
    const float* bias = (const float*)d_in[4];   // [256]
    float* out = (float*)d_out;                  // [16,256,1024]

    cudaFuncSetAttribute(argmin_kernel, cudaFuncAttributeMaxDynamicSharedMemorySize, 65536);
    cudaFuncSetAttribute(gather_kernel, cudaFuncAttributeMaxDynamicSharedMemorySize, 69632);
    cudaFuncSetAttribute(gemm_kernel, cudaFuncAttributeMaxDynamicSharedMemorySize, GEMM_SMEM);

    argmin_kernel<<<256, 256, 65536>>>(seed, pl);
    wsplit_kernel<<<(O_ * C_ + 255) / 256, 256>>>(Wt);
    gather_kernel<<<B_ * 192, 256, 69632>>>(fl);
    gemm_kernel<<<dim3(M_ / 128, O_ / 64), 256, GEMM_SMEM>>>(bias, out);
}